// round 5
// baseline (speedup 1.0000x reference)
#include <cuda_runtime.h>
#include <cstddef>
#include <cstdint>

// Problem constants
#define CB   16          // batch
#define CS   4096        // seqlen
#define CD   768         // dim
#define CH   12          // heads
#define HD   64          // head dim
#define CKS  9           // conv kernel size
#define CPAD 4           // conv padding
#define NQKV (3*CD)      // 2304
#define MTOT (CB*CS)     // 65536

// Scratch (no allocations allowed; __device__ globals instead)
__device__ float g_qkv[(size_t)MTOT * NQKV];       // [B*S, 3D]  (~604MB)
__device__ float g_att[(size_t)MTOT * CD];         // [B*S, D]   (~201MB)
__device__ float g_kv [(size_t)CB * CH * HD * HD]; // [B,H,64,64] (3MB)

// ----------------------------------------------------------------------------
// tf32 + async-copy helpers
// ----------------------------------------------------------------------------
__device__ __forceinline__ uint32_t f2tf32(float f) {
    uint32_t u;
    asm("cvt.rna.tf32.f32 %0, %1;" : "=r"(u) : "f"(f));
    return u;
}

// split x into tf32 hi + tf32 lo (3xTF32 scheme; float(hi) subtraction is exact)
__device__ __forceinline__ void split_tf32(float x, uint32_t& hi, uint32_t& lo) {
    hi = f2tf32(x);
    lo = f2tf32(x - __uint_as_float(hi));
}

__device__ __forceinline__ void mma_tf32(float c[4],
                                         uint32_t a0, uint32_t a1, uint32_t a2, uint32_t a3,
                                         uint32_t b0, uint32_t b1) {
    asm volatile(
        "mma.sync.aligned.m16n8k8.row.col.f32.tf32.tf32.f32 "
        "{%0,%1,%2,%3}, {%4,%5,%6,%7}, {%8,%9}, {%0,%1,%2,%3};\n"
        : "+f"(c[0]), "+f"(c[1]), "+f"(c[2]), "+f"(c[3])
        : "r"(a0), "r"(a1), "r"(a2), "r"(a3), "r"(b0), "r"(b1));
}

__device__ __forceinline__ void cp16(uint32_t smem_dst, const void* gptr) {
    asm volatile("cp.async.cg.shared.global [%0], [%1], 16;\n"
                 :: "r"(smem_dst), "l"(gptr));
}

// ----------------------------------------------------------------------------
// 3xTF32 tensor-core GEMM (fp32-accurate): C[M,N] = A[M,K] @ W[N,K]^T + bias[N]
// BM=128, BN=128, BK=32. 256 threads = 8 warps in 2(m) x 4(n); warp tile 64x32.
// cp.async 3-stage ring buffer; padded smem stride 36 (conflict-free LDS).
// D += Ahi*Bhi + Alo*Bhi + Ahi*Blo   (lo*lo term ~2^-22 dropped)
// Requires M%128==0, N%128==0, K%32==0.
// ----------------------------------------------------------------------------
#define GBK 32
#define NSTAGE 3
#define SSTR 36                         // smem row stride in floats (pad 32->36)
#define SBUF (128 * SSTR)               // one matrix buffer, floats (18KB)
#define SMEM_BYTES (2 * NSTAGE * SBUF * 4)  // A+B x 3 stages = 110592 B

__global__ __launch_bounds__(256) void gemm_tf32x3_kernel(
    const float* __restrict__ A, const float* __restrict__ W,
    const float* __restrict__ bias, float* __restrict__ C,
    int M, int N, int K)
{
    extern __shared__ float smem[];
    float* As = smem;                      // [NSTAGE][128][SSTR]
    float* Bs = smem + NSTAGE * SBUF;      // [NSTAGE][128][SSTR]
    const uint32_t smem_u32 = (uint32_t)__cvta_generic_to_shared(smem);

    const int tid   = threadIdx.x;
    const int lane  = tid & 31;
    const int warp  = tid >> 5;
    const int wm    = (warp >> 2) * 64;   // warp m-offset (0 or 64)
    const int wn    = (warp & 3) * 32;    // warp n-offset (0..96)
    const int bm    = blockIdx.y * 128;
    const int bn    = blockIdx.x * 128;

    // global load mapping: 4 passes; row = p*32 + tid/8, k4 = (tid&7)*4
    const int lr  = tid >> 3;        // 0..31
    const int lk4 = (tid & 7) * 4;   // 0..28

    const float* Ap = A + (size_t)(bm + lr) * K + lk4;
    const float* Wp = W + (size_t)(bn + lr) * K + lk4;
    const uint32_t soA = smem_u32 + (uint32_t)((lr * SSTR + lk4) * 4);
    const uint32_t soB = soA + (uint32_t)(NSTAGE * SBUF * 4);

    float acc[4][4][4];
#pragma unroll
    for (int i = 0; i < 4; i++)
#pragma unroll
        for (int j = 0; j < 4; j++)
#pragma unroll
            for (int c = 0; c < 4; c++) acc[i][j][c] = 0.0f;

    const int T = K / GBK;

#define LOAD_TILE(t, buf)                                                      \
    do {                                                                       \
        const float* Apt = Ap + (size_t)(t) * GBK;                             \
        const float* Wpt = Wp + (size_t)(t) * GBK;                             \
        const uint32_t bo = (uint32_t)((buf) * SBUF * 4);                      \
        _Pragma("unroll")                                                      \
        for (int p = 0; p < 4; p++) {                                          \
            cp16(soA + bo + (uint32_t)(p * 32 * SSTR * 4),                     \
                 Apt + (size_t)(p * 32) * K);                                  \
            cp16(soB + bo + (uint32_t)(p * 32 * SSTR * 4),                     \
                 Wpt + (size_t)(p * 32) * K);                                  \
        }                                                                      \
        asm volatile("cp.async.commit_group;\n" ::: "memory");                 \
    } while (0)

    // prime 2 stages (T >= 2 always: K >= 64)
    LOAD_TILE(0, 0);
    LOAD_TILE(1, 1);

    int buf = 0;
    for (int t = 0; t < T; t++) {
        // keep two tiles in flight; tail-correct waits
        if (t + 2 < T) {
            LOAD_TILE(t + 2, (buf + 2) % NSTAGE);
            asm volatile("cp.async.wait_group 2;\n" ::: "memory");
        } else if (t + 1 < T) {
            asm volatile("cp.async.wait_group 1;\n" ::: "memory");
        } else {
            asm volatile("cp.async.wait_group 0;\n" ::: "memory");
        }
        __syncthreads();

        const float* Asc = As + buf * SBUF;
        const float* Bsc = Bs + buf * SBUF;
#pragma unroll
        for (int ks = 0; ks < 4; ks++) {
            const int k0 = ks * 8;

            // load fp32 fragments from smem
            float a32[4][4];
            float b32[4][2];
#pragma unroll
            for (int am = 0; am < 4; am++) {
                int r0 = wm + am * 16 + (lane >> 2);
                int c0 = k0 + (lane & 3);
                a32[am][0] = Asc[r0 * SSTR + c0];
                a32[am][1] = Asc[(r0 + 8) * SSTR + c0];
                a32[am][2] = Asc[r0 * SSTR + c0 + 4];
                a32[am][3] = Asc[(r0 + 8) * SSTR + c0 + 4];
            }
#pragma unroll
            for (int bnn = 0; bnn < 4; bnn++) {
                int col = wn + bnn * 8 + (lane >> 2);
                int kk  = k0 + (lane & 3);
                b32[bnn][0] = Bsc[col * SSTR + kk];
                b32[bnn][1] = Bsc[col * SSTR + kk + 4];
            }

            // split into tf32 hi/lo
            uint32_t ahi[4][4], alo[4][4], bhi[4][2], blo[4][2];
#pragma unroll
            for (int am = 0; am < 4; am++)
#pragma unroll
                for (int e = 0; e < 4; e++)
                    split_tf32(a32[am][e], ahi[am][e], alo[am][e]);
#pragma unroll
            for (int bnn = 0; bnn < 4; bnn++)
#pragma unroll
                for (int e = 0; e < 2; e++)
                    split_tf32(b32[bnn][e], bhi[bnn][e], blo[bnn][e]);

            // pass 1: hi x hi
#pragma unroll
            for (int am = 0; am < 4; am++)
#pragma unroll
                for (int bnn = 0; bnn < 4; bnn++)
                    mma_tf32(acc[am][bnn],
                             ahi[am][0], ahi[am][1], ahi[am][2], ahi[am][3],
                             bhi[bnn][0], bhi[bnn][1]);
            // pass 2: lo x hi
#pragma unroll
            for (int am = 0; am < 4; am++)
#pragma unroll
                for (int bnn = 0; bnn < 4; bnn++)
                    mma_tf32(acc[am][bnn],
                             alo[am][0], alo[am][1], alo[am][2], alo[am][3],
                             bhi[bnn][0], bhi[bnn][1]);
            // pass 3: hi x lo
#pragma unroll
            for (int am = 0; am < 4; am++)
#pragma unroll
                for (int bnn = 0; bnn < 4; bnn++)
                    mma_tf32(acc[am][bnn],
                             ahi[am][0], ahi[am][1], ahi[am][2], ahi[am][3],
                             blo[bnn][0], blo[bnn][1]);
        }
        __syncthreads();
        buf = (buf + 1) % NSTAGE;
    }

    // epilogue: rows = bm+wm+am*16+lane/4 (+8), cols = bn+wn+bnn*8+(lane%4)*2 (+1)
    float bv0[4], bv1[4];
#pragma unroll
    for (int bnn = 0; bnn < 4; bnn++) {
        int c0 = bn + wn + bnn * 8 + (lane & 3) * 2;
        bv0[bnn] = __ldg(&bias[c0]);
        bv1[bnn] = __ldg(&bias[c0 + 1]);
    }
#pragma unroll
    for (int am = 0; am < 4; am++) {
        int r0 = bm + wm + am * 16 + (lane >> 2);
#pragma unroll
        for (int bnn = 0; bnn < 4; bnn++) {
            int c0 = bn + wn + bnn * 8 + (lane & 3) * 2;
            float2 v01 = make_float2(acc[am][bnn][0] + bv0[bnn], acc[am][bnn][1] + bv1[bnn]);
            float2 v23 = make_float2(acc[am][bnn][2] + bv0[bnn], acc[am][bnn][3] + bv1[bnn]);
            *(float2*)&C[(size_t)r0 * N + c0]       = v01;
            *(float2*)&C[(size_t)(r0 + 8) * N + c0] = v23;
        }
    }
}

// ----------------------------------------------------------------------------
// kv kernel: one block per (b,h). kv[d][e] = sum_s khat[s,d] * v[s,e]
// khat = k / ||k||_2 per row. 256 threads, 32-row S tiles, 4x4 microtile. fp32.
// ----------------------------------------------------------------------------
__global__ __launch_bounds__(256) void kv_kernel()
{
    int bh = blockIdx.x;
    int b = bh / CH, h = bh % CH;
    const float* kbase = g_qkv + (size_t)b * CS * NQKV + CD     + h * HD;
    const float* vbase = g_qkv + (size_t)b * CS * NQKV + 2 * CD + h * HD;

    __shared__ float ks[32][HD];
    __shared__ float vs[32][HD];

    int tid  = threadIdx.x;
    int lane = tid & 31;
    int warp = tid >> 5;
    int ti = tid >> 4;   // 0..15
    int tj = tid & 15;   // 0..15

    float acc[4][4];
#pragma unroll
    for (int i = 0; i < 4; i++)
#pragma unroll
        for (int j = 0; j < 4; j++) acc[i][j] = 0.0f;

    for (int t0 = 0; t0 < CS; t0 += 32) {
        for (int i = tid; i < 32 * HD; i += 256) {
            int s = i >> 6, dd = i & 63;
            ks[s][dd] = kbase[(size_t)(t0 + s) * NQKV + dd];
            vs[s][dd] = vbase[(size_t)(t0 + s) * NQKV + dd];
        }
        __syncthreads();

#pragma unroll
        for (int rr = 0; rr < 4; rr++) {
            int r = warp * 4 + rr;
            float a = ks[r][lane], c = ks[r][lane + 32];
            float ns = a * a + c * c;
#pragma unroll
            for (int o = 16; o > 0; o >>= 1)
                ns += __shfl_xor_sync(0xffffffffu, ns, o);
            float inv = rsqrtf(ns);
            ks[r][lane] = a * inv;
            ks[r][lane + 32] = c * inv;
        }
        __syncthreads();

#pragma unroll 8
        for (int s = 0; s < 32; s++) {
            float4 ka = *(const float4*)&ks[s][ti * 4];
            float4 vb = *(const float4*)&vs[s][tj * 4];
            float kr[4] = {ka.x, ka.y, ka.z, ka.w};
            float vr[4] = {vb.x, vb.y, vb.z, vb.w};
#pragma unroll
            for (int i = 0; i < 4; i++)
#pragma unroll
                for (int j = 0; j < 4; j++)
                    acc[i][j] += kr[i] * vr[j];
        }
        __syncthreads();
    }

    float* kvout = g_kv + (size_t)bh * HD * HD;
#pragma unroll
    for (int i = 0; i < 4; i++)
#pragma unroll
        for (int j = 0; j < 4; j++)
            kvout[(ti * 4 + i) * HD + tj * 4 + j] = acc[i][j];
}

// ----------------------------------------------------------------------------
// out kernel: qhat = q/||q||; a = qhat@kv; o = 0.5v + (1/pi)a; o/=||o||;
// o += depthwise_conv9(v); write transposed into g_att [B,S,D]. fp32.
// ----------------------------------------------------------------------------
__global__ __launch_bounds__(256) void out_kernel(const float* __restrict__ wdconv)
{
    int bh = blockIdx.x;
    int b = bh / CH, h = bh % CH;
    int s0 = blockIdx.y * 128;

    __shared__ float kvs[HD * HD];
    __shared__ float wconv[CKS];

    int tid = threadIdx.x;
    int lane = tid & 31;
    int warp = tid >> 5;

    for (int i = tid; i < HD * HD; i += 256)
        kvs[i] = g_kv[(size_t)bh * HD * HD + i];
    if (tid < CKS) wconv[tid] = wdconv[h * CKS + tid];
    __syncthreads();

    const float* qbase = g_qkv + (size_t)b * CS * NQKV + h * HD;
    const float* vbase = g_qkv + (size_t)b * CS * NQKV + 2 * CD + h * HD;
    const float invpi = 0.31830988618379067f;

    for (int r = warp; r < 128; r += 8) {
        int s = s0 + r;
        const float* qrow = qbase + (size_t)s * NQKV;
        const float* vrow = vbase + (size_t)s * NQKV;

        float q0 = qrow[lane], q1 = qrow[lane + 32];
        float nq = q0 * q0 + q1 * q1;
#pragma unroll
        for (int o = 16; o > 0; o >>= 1)
            nq += __shfl_xor_sync(0xffffffffu, nq, o);
        float inq = rsqrtf(nq);
        q0 *= inq; q1 *= inq;

        float a0 = 0.0f, a1 = 0.0f;
#pragma unroll
        for (int dd = 0; dd < 32; dd++) {
            float qv = __shfl_sync(0xffffffffu, q0, dd);
            a0 += qv * kvs[dd * HD + lane];
            a1 += qv * kvs[dd * HD + lane + 32];
        }
#pragma unroll
        for (int dd = 0; dd < 32; dd++) {
            float qv = __shfl_sync(0xffffffffu, q1, dd);
            a0 += qv * kvs[(dd + 32) * HD + lane];
            a1 += qv * kvs[(dd + 32) * HD + lane + 32];
        }

        float v0 = vrow[lane], v1 = vrow[lane + 32];
        float o0 = 0.5f * v0 + invpi * a0;
        float o1 = 0.5f * v1 + invpi * a1;
        float no = o0 * o0 + o1 * o1;
#pragma unroll
        for (int o = 16; o > 0; o >>= 1)
            no += __shfl_xor_sync(0xffffffffu, no, o);
        float ino = rsqrtf(no);
        o0 *= ino; o1 *= ino;

        float c0 = 0.0f, c1 = 0.0f;
#pragma unroll
        for (int t = 0; t < CKS; t++) {
            int ss = s + t - CPAD;
            if (ss >= 0 && ss < CS) {
                const float* vr = vbase + (size_t)ss * NQKV;
                float w = wconv[t];
                c0 += w * vr[lane];
                c1 += w * vr[lane + 32];
            }
        }
        o0 += c0; o1 += c1;

        float* orow = g_att + (size_t)(b * CS + s) * CD + h * HD;
        orow[lane] = o0;
        orow[lane + 32] = o1;
    }
}

// ----------------------------------------------------------------------------
// Launch
// ----------------------------------------------------------------------------
extern "C" void kernel_launch(void* const* d_in, const int* in_sizes, int n_in,
                              void* d_out, int out_size)
{
    (void)in_sizes; (void)n_in; (void)out_size;
    const float* x      = (const float*)d_in[0];
    const float* w_qkv  = (const float*)d_in[1];
    const float* b_qkv  = (const float*)d_in[2];
    const float* w_proj = (const float*)d_in[3];
    const float* b_proj = (const float*)d_in[4];
    const float* wdconv = (const float*)d_in[5];
    float* out = (float*)d_out;

    float *qkv_ptr = nullptr, *att_ptr = nullptr;
    cudaGetSymbolAddress((void**)&qkv_ptr, g_qkv);
    cudaGetSymbolAddress((void**)&att_ptr, g_att);

    // Unconditional (no static guards allowed). Host-side, capture-safe.
    cudaFuncSetAttribute(gemm_tf32x3_kernel,
                         cudaFuncAttributeMaxDynamicSharedMemorySize, SMEM_BYTES);

    dim3 blk(256);

    // 1) QKV projection: [65536,2304] = x[65536,768] @ w_qkv^T + b
    dim3 g1(NQKV / 128, MTOT / 128);
    gemm_tf32x3_kernel<<<g1, blk, SMEM_BYTES>>>(x, w_qkv, b_qkv, qkv_ptr, MTOT, NQKV, CD);

    // 2) kv = khat^T v per (b,h)
    kv_kernel<<<CB * CH, blk>>>();

    // 3) attention epilogue + conv + transpose
    dim3 g3(CB * CH, CS / 128);
    out_kernel<<<g3, blk>>>(wdconv);

    // 4) output projection: [65536,768] = att @ w_proj^T + b
    dim3 g4(CD / 128, MTOT / 128);
    gemm_tf32x3_kernel<<<g4, blk, SMEM_BYTES>>>(att_ptr, w_proj, b_proj, out, MTOT, CD, CD);
}

// round 6
// speedup vs baseline: 1.9672x; 1.9672x over previous
#include <cuda_runtime.h>
#include <cstddef>
#include <cstdint>

// Problem constants
#define CB   16          // batch
#define CS   4096        // seqlen
#define CD   768         // dim
#define CH   12          // heads
#define HD   64          // head dim
#define CKS  9           // conv kernel size
#define CPAD 4           // conv padding
#define NQKV (3*CD)      // 2304
#define MTOT (CB*CS)     // 65536

// Scratch (no allocations allowed; __device__ globals instead)
__device__ float g_qkv[(size_t)MTOT * NQKV];       // [B*S, 3D]  (~604MB)
__device__ float g_att[(size_t)MTOT * CD];         // [B*S, D]   (~201MB)
__device__ float g_kv [(size_t)CB * CH * HD * HD]; // [B,H,64,64] (3MB)

// ----------------------------------------------------------------------------
// tf32 + async-copy helpers
// ----------------------------------------------------------------------------
__device__ __forceinline__ uint32_t f2tf32(float f) {
    uint32_t u;
    asm("cvt.rna.tf32.f32 %0, %1;" : "=r"(u) : "f"(f));
    return u;
}

__device__ __forceinline__ void mma_tf32(float c[4],
                                         uint32_t a0, uint32_t a1, uint32_t a2, uint32_t a3,
                                         uint32_t b0, uint32_t b1) {
    asm volatile(
        "mma.sync.aligned.m16n8k8.row.col.f32.tf32.tf32.f32 "
        "{%0,%1,%2,%3}, {%4,%5,%6,%7}, {%8,%9}, {%0,%1,%2,%3};\n"
        : "+f"(c[0]), "+f"(c[1]), "+f"(c[2]), "+f"(c[3])
        : "r"(a0), "r"(a1), "r"(a2), "r"(a3), "r"(b0), "r"(b1));
}

__device__ __forceinline__ void cp16(uint32_t smem_dst, const void* gptr) {
    asm volatile("cp.async.cg.shared.global [%0], [%1], 16;\n"
                 :: "r"(smem_dst), "l"(gptr));
}

// ----------------------------------------------------------------------------
// 1xTF32 tensor-core GEMM: C[M,N] = A[M,K] @ W[N,K]^T + bias[N]
// BM=128, BN=128, BK=32. 256 threads = 8 warps in 2(m) x 4(n); warp tile 64x32.
// cp.async 3-stage ring buffer; padded smem stride 36 (conflict-free LDS).
// 2 CTAs/SM target (221KB smem, ~100 regs).
// Requires M%128==0, N%128==0, K%32==0.
// ----------------------------------------------------------------------------
#define GBK 32
#define NSTAGE 3
#define SSTR 36                         // smem row stride in floats (pad 32->36)
#define SBUF (128 * SSTR)               // one matrix buffer, floats (18KB)
#define SMEM_BYTES (2 * NSTAGE * SBUF * 4)  // A+B x 3 stages = 110592 B

__global__ __launch_bounds__(256, 2) void gemm_tf32_kernel(
    const float* __restrict__ A, const float* __restrict__ W,
    const float* __restrict__ bias, float* __restrict__ C,
    int M, int N, int K)
{
    extern __shared__ float smem[];
    float* As = smem;                      // [NSTAGE][128][SSTR]
    float* Bs = smem + NSTAGE * SBUF;      // [NSTAGE][128][SSTR]
    const uint32_t smem_u32 = (uint32_t)__cvta_generic_to_shared(smem);

    const int tid   = threadIdx.x;
    const int lane  = tid & 31;
    const int warp  = tid >> 5;
    const int wm    = (warp >> 2) * 64;   // warp m-offset (0 or 64)
    const int wn    = (warp & 3) * 32;    // warp n-offset (0..96)
    const int bm    = blockIdx.y * 128;
    const int bn    = blockIdx.x * 128;

    // global load mapping: 4 passes; row = p*32 + tid/8, k4 = (tid&7)*4
    const int lr  = tid >> 3;        // 0..31
    const int lk4 = (tid & 7) * 4;   // 0..28

    const float* Ap = A + (size_t)(bm + lr) * K + lk4;
    const float* Wp = W + (size_t)(bn + lr) * K + lk4;
    const uint32_t soA = smem_u32 + (uint32_t)((lr * SSTR + lk4) * 4);
    const uint32_t soB = soA + (uint32_t)(NSTAGE * SBUF * 4);

    float acc[4][4][4];
#pragma unroll
    for (int i = 0; i < 4; i++)
#pragma unroll
        for (int j = 0; j < 4; j++)
#pragma unroll
            for (int c = 0; c < 4; c++) acc[i][j][c] = 0.0f;

    const int T = K / GBK;

#define LOAD_TILE(t, buf)                                                      \
    do {                                                                       \
        const float* Apt = Ap + (size_t)(t) * GBK;                             \
        const float* Wpt = Wp + (size_t)(t) * GBK;                             \
        const uint32_t bo = (uint32_t)((buf) * SBUF * 4);                      \
        _Pragma("unroll")                                                      \
        for (int p = 0; p < 4; p++) {                                          \
            cp16(soA + bo + (uint32_t)(p * 32 * SSTR * 4),                     \
                 Apt + (size_t)(p * 32) * K);                                  \
            cp16(soB + bo + (uint32_t)(p * 32 * SSTR * 4),                     \
                 Wpt + (size_t)(p * 32) * K);                                  \
        }                                                                      \
        asm volatile("cp.async.commit_group;\n" ::: "memory");                 \
    } while (0)

    // prime 2 stages (T >= 2 always: K >= 64)
    LOAD_TILE(0, 0);
    LOAD_TILE(1, 1);

    int buf = 0;
    for (int t = 0; t < T; t++) {
        // keep two tiles in flight; tail-correct waits
        if (t + 2 < T) {
            LOAD_TILE(t + 2, (buf + 2) % NSTAGE);
            asm volatile("cp.async.wait_group 2;\n" ::: "memory");
        } else if (t + 1 < T) {
            asm volatile("cp.async.wait_group 1;\n" ::: "memory");
        } else {
            asm volatile("cp.async.wait_group 0;\n" ::: "memory");
        }
        __syncthreads();

        const float* Asc = As + buf * SBUF;
        const float* Bsc = Bs + buf * SBUF;
#pragma unroll
        for (int ks = 0; ks < 4; ks++) {
            const int k0 = ks * 8;

            // load + convert fragments straight from smem (1x tf32)
            uint32_t af[4][4];
            uint32_t bf[4][2];
#pragma unroll
            for (int am = 0; am < 4; am++) {
                int r0 = wm + am * 16 + (lane >> 2);
                int c0 = k0 + (lane & 3);
                af[am][0] = f2tf32(Asc[r0 * SSTR + c0]);
                af[am][1] = f2tf32(Asc[(r0 + 8) * SSTR + c0]);
                af[am][2] = f2tf32(Asc[r0 * SSTR + c0 + 4]);
                af[am][3] = f2tf32(Asc[(r0 + 8) * SSTR + c0 + 4]);
            }
#pragma unroll
            for (int bnn = 0; bnn < 4; bnn++) {
                int col = wn + bnn * 8 + (lane >> 2);
                int kk  = k0 + (lane & 3);
                bf[bnn][0] = f2tf32(Bsc[col * SSTR + kk]);
                bf[bnn][1] = f2tf32(Bsc[col * SSTR + kk + 4]);
            }
#pragma unroll
            for (int am = 0; am < 4; am++)
#pragma unroll
                for (int bnn = 0; bnn < 4; bnn++)
                    mma_tf32(acc[am][bnn],
                             af[am][0], af[am][1], af[am][2], af[am][3],
                             bf[bnn][0], bf[bnn][1]);
        }
        __syncthreads();
        buf = (buf + 1) % NSTAGE;
    }

    // epilogue: rows = bm+wm+am*16+lane/4 (+8), cols = bn+wn+bnn*8+(lane%4)*2 (+1)
    float bv0[4], bv1[4];
#pragma unroll
    for (int bnn = 0; bnn < 4; bnn++) {
        int c0 = bn + wn + bnn * 8 + (lane & 3) * 2;
        bv0[bnn] = __ldg(&bias[c0]);
        bv1[bnn] = __ldg(&bias[c0 + 1]);
    }
#pragma unroll
    for (int am = 0; am < 4; am++) {
        int r0 = bm + wm + am * 16 + (lane >> 2);
#pragma unroll
        for (int bnn = 0; bnn < 4; bnn++) {
            int c0 = bn + wn + bnn * 8 + (lane & 3) * 2;
            float2 v01 = make_float2(acc[am][bnn][0] + bv0[bnn], acc[am][bnn][1] + bv1[bnn]);
            float2 v23 = make_float2(acc[am][bnn][2] + bv0[bnn], acc[am][bnn][3] + bv1[bnn]);
            *(float2*)&C[(size_t)r0 * N + c0]       = v01;
            *(float2*)&C[(size_t)(r0 + 8) * N + c0] = v23;
        }
    }
}

// ----------------------------------------------------------------------------
// kv kernel: one block per (b,h). kv[d][e] = sum_s khat[s,d] * v[s,e]
// khat = k / ||k||_2 per row. 256 threads, 32-row S tiles, 4x4 microtile. fp32.
// ----------------------------------------------------------------------------
__global__ __launch_bounds__(256) void kv_kernel()
{
    int bh = blockIdx.x;
    int b = bh / CH, h = bh % CH;
    const float* kbase = g_qkv + (size_t)b * CS * NQKV + CD     + h * HD;
    const float* vbase = g_qkv + (size_t)b * CS * NQKV + 2 * CD + h * HD;

    __shared__ float ks[32][HD];
    __shared__ float vs[32][HD];

    int tid  = threadIdx.x;
    int lane = tid & 31;
    int warp = tid >> 5;
    int ti = tid >> 4;   // 0..15
    int tj = tid & 15;   // 0..15

    float acc[4][4];
#pragma unroll
    for (int i = 0; i < 4; i++)
#pragma unroll
        for (int j = 0; j < 4; j++) acc[i][j] = 0.0f;

    for (int t0 = 0; t0 < CS; t0 += 32) {
        for (int i = tid; i < 32 * HD; i += 256) {
            int s = i >> 6, dd = i & 63;
            ks[s][dd] = kbase[(size_t)(t0 + s) * NQKV + dd];
            vs[s][dd] = vbase[(size_t)(t0 + s) * NQKV + dd];
        }
        __syncthreads();

#pragma unroll
        for (int rr = 0; rr < 4; rr++) {
            int r = warp * 4 + rr;
            float a = ks[r][lane], c = ks[r][lane + 32];
            float ns = a * a + c * c;
#pragma unroll
            for (int o = 16; o > 0; o >>= 1)
                ns += __shfl_xor_sync(0xffffffffu, ns, o);
            float inv = rsqrtf(ns);
            ks[r][lane] = a * inv;
            ks[r][lane + 32] = c * inv;
        }
        __syncthreads();

#pragma unroll 8
        for (int s = 0; s < 32; s++) {
            float4 ka = *(const float4*)&ks[s][ti * 4];
            float4 vb = *(const float4*)&vs[s][tj * 4];
            float kr[4] = {ka.x, ka.y, ka.z, ka.w};
            float vr[4] = {vb.x, vb.y, vb.z, vb.w};
#pragma unroll
            for (int i = 0; i < 4; i++)
#pragma unroll
                for (int j = 0; j < 4; j++)
                    acc[i][j] += kr[i] * vr[j];
        }
        __syncthreads();
    }

    float* kvout = g_kv + (size_t)bh * HD * HD;
#pragma unroll
    for (int i = 0; i < 4; i++)
#pragma unroll
        for (int j = 0; j < 4; j++)
            kvout[(ti * 4 + i) * HD + tj * 4 + j] = acc[i][j];
}

// ----------------------------------------------------------------------------
// out kernel: qhat = q/||q||; a = qhat@kv; o = 0.5v + (1/pi)a; o/=||o||;
// o += depthwise_conv9(v); write transposed into g_att [B,S,D]. fp32.
// ----------------------------------------------------------------------------
__global__ __launch_bounds__(256) void out_kernel(const float* __restrict__ wdconv)
{
    int bh = blockIdx.x;
    int b = bh / CH, h = bh % CH;
    int s0 = blockIdx.y * 128;

    __shared__ float kvs[HD * HD];
    __shared__ float wconv[CKS];

    int tid = threadIdx.x;
    int lane = tid & 31;
    int warp = tid >> 5;

    for (int i = tid; i < HD * HD; i += 256)
        kvs[i] = g_kv[(size_t)bh * HD * HD + i];
    if (tid < CKS) wconv[tid] = wdconv[h * CKS + tid];
    __syncthreads();

    const float* qbase = g_qkv + (size_t)b * CS * NQKV + h * HD;
    const float* vbase = g_qkv + (size_t)b * CS * NQKV + 2 * CD + h * HD;
    const float invpi = 0.31830988618379067f;

    for (int r = warp; r < 128; r += 8) {
        int s = s0 + r;
        const float* qrow = qbase + (size_t)s * NQKV;
        const float* vrow = vbase + (size_t)s * NQKV;

        float q0 = qrow[lane], q1 = qrow[lane + 32];
        float nq = q0 * q0 + q1 * q1;
#pragma unroll
        for (int o = 16; o > 0; o >>= 1)
            nq += __shfl_xor_sync(0xffffffffu, nq, o);
        float inq = rsqrtf(nq);
        q0 *= inq; q1 *= inq;

        float a0 = 0.0f, a1 = 0.0f;
#pragma unroll
        for (int dd = 0; dd < 32; dd++) {
            float qv = __shfl_sync(0xffffffffu, q0, dd);
            a0 += qv * kvs[dd * HD + lane];
            a1 += qv * kvs[dd * HD + lane + 32];
        }
#pragma unroll
        for (int dd = 0; dd < 32; dd++) {
            float qv = __shfl_sync(0xffffffffu, q1, dd);
            a0 += qv * kvs[(dd + 32) * HD + lane];
            a1 += qv * kvs[(dd + 32) * HD + lane + 32];
        }

        float v0 = vrow[lane], v1 = vrow[lane + 32];
        float o0 = 0.5f * v0 + invpi * a0;
        float o1 = 0.5f * v1 + invpi * a1;
        float no = o0 * o0 + o1 * o1;
#pragma unroll
        for (int o = 16; o > 0; o >>= 1)
            no += __shfl_xor_sync(0xffffffffu, no, o);
        float ino = rsqrtf(no);
        o0 *= ino; o1 *= ino;

        float c0 = 0.0f, c1 = 0.0f;
#pragma unroll
        for (int t = 0; t < CKS; t++) {
            int ss = s + t - CPAD;
            if (ss >= 0 && ss < CS) {
                const float* vr = vbase + (size_t)ss * NQKV;
                float w = wconv[t];
                c0 += w * vr[lane];
                c1 += w * vr[lane + 32];
            }
        }
        o0 += c0; o1 += c1;

        float* orow = g_att + (size_t)(b * CS + s) * CD + h * HD;
        orow[lane] = o0;
        orow[lane + 32] = o1;
    }
}

// ----------------------------------------------------------------------------
// Launch
// ----------------------------------------------------------------------------
extern "C" void kernel_launch(void* const* d_in, const int* in_sizes, int n_in,
                              void* d_out, int out_size)
{
    (void)in_sizes; (void)n_in; (void)out_size;
    const float* x      = (const float*)d_in[0];
    const float* w_qkv  = (const float*)d_in[1];
    const float* b_qkv  = (const float*)d_in[2];
    const float* w_proj = (const float*)d_in[3];
    const float* b_proj = (const float*)d_in[4];
    const float* wdconv = (const float*)d_in[5];
    float* out = (float*)d_out;

    float *qkv_ptr = nullptr, *att_ptr = nullptr;
    cudaGetSymbolAddress((void**)&qkv_ptr, g_qkv);
    cudaGetSymbolAddress((void**)&att_ptr, g_att);

    // Unconditional (no static guards allowed). Host-side, capture-safe.
    cudaFuncSetAttribute(gemm_tf32_kernel,
                         cudaFuncAttributeMaxDynamicSharedMemorySize, SMEM_BYTES);

    dim3 blk(256);

    // 1) QKV projection: [65536,2304] = x[65536,768] @ w_qkv^T + b
    dim3 g1(NQKV / 128, MTOT / 128);
    gemm_tf32_kernel<<<g1, blk, SMEM_BYTES>>>(x, w_qkv, b_qkv, qkv_ptr, MTOT, NQKV, CD);

    // 2) kv = khat^T v per (b,h)
    kv_kernel<<<CB * CH, blk>>>();

    // 3) attention epilogue + conv + transpose
    dim3 g3(CB * CH, CS / 128);
    out_kernel<<<g3, blk>>>(wdconv);

    // 4) output projection: [65536,768] = att @ w_proj^T + b
    dim3 g4(CD / 128, MTOT / 128);
    gemm_tf32_kernel<<<g4, blk, SMEM_BYTES>>>(att_ptr, w_proj, b_proj, out, MTOT, CD, CD);
}

// round 15
// speedup vs baseline: 2.1355x; 1.0856x over previous
#include <cuda_runtime.h>
#include <cstddef>
#include <cstdint>

// Problem constants
#define CB   16          // batch
#define CS   4096        // seqlen
#define CD   768         // dim
#define CH   12          // heads
#define HD   64          // head dim
#define CKS  9           // conv kernel size
#define CPAD 4           // conv padding
#define NQKV (3*CD)      // 2304
#define MTOT (CB*CS)     // 65536

// Scratch (no allocations allowed; __device__ globals instead)
__device__ float g_qkv[(size_t)MTOT * NQKV];       // [B*S, 3D]  (~604MB)
__device__ float g_att[(size_t)MTOT * CD];         // [B*S, D]   (~201MB) tf32-rounded
__device__ float g_kv [(size_t)CB * CH * HD * HD]; // [B,H,64,64] (3MB)
__device__ float g_xt [(size_t)MTOT * CD];         // tf32-rounded x (~201MB)
__device__ float g_wq [(size_t)NQKV * CD];         // tf32-rounded w_qkv (7MB)
__device__ float g_wp [(size_t)CD * CD];           // tf32-rounded w_proj (2.25MB)

// ----------------------------------------------------------------------------
// tf32 + async-copy helpers
// ----------------------------------------------------------------------------
__device__ __forceinline__ uint32_t f2tf32(float f) {
    uint32_t u;
    asm("cvt.rna.tf32.f32 %0, %1;" : "=r"(u) : "f"(f));
    return u;
}

__device__ __forceinline__ void mma_tf32(float c[4],
                                         uint32_t a0, uint32_t a1, uint32_t a2, uint32_t a3,
                                         uint32_t b0, uint32_t b1) {
    asm volatile(
        "mma.sync.aligned.m16n8k8.row.col.f32.tf32.tf32.f32 "
        "{%0,%1,%2,%3}, {%4,%5,%6,%7}, {%8,%9}, {%0,%1,%2,%3};\n"
        : "+f"(c[0]), "+f"(c[1]), "+f"(c[2]), "+f"(c[3])
        : "r"(a0), "r"(a1), "r"(a2), "r"(a3), "r"(b0), "r"(b1));
}

__device__ __forceinline__ void cp16(uint32_t smem_dst, const void* gptr) {
    asm volatile("cp.async.cg.shared.global [%0], [%1], 16;\n"
                 :: "r"(smem_dst), "l"(gptr));
}

// ----------------------------------------------------------------------------
// elementwise tf32-round kernel: dst[i] = round_tf32(src[i]) (as fp32 bits)
// ----------------------------------------------------------------------------
__global__ __launch_bounds__(256) void cvt_tf32_kernel(
    const float* __restrict__ src, float* __restrict__ dst, size_t n4)
{
    size_t i = (size_t)blockIdx.x * blockDim.x + threadIdx.x;
    if (i < n4) {
        float4 v = ((const float4*)src)[i];
        v.x = __uint_as_float(f2tf32(v.x));
        v.y = __uint_as_float(f2tf32(v.y));
        v.z = __uint_as_float(f2tf32(v.z));
        v.w = __uint_as_float(f2tf32(v.w));
        ((float4*)dst)[i] = v;
    }
}

// ----------------------------------------------------------------------------
// TF32 tensor-core GEMM (operands pre-rounded to tf32): C = A @ W^T + bias
// BM=128, BN=128, BK=32. 256 threads = 8 warps in 2(m) x 4(n); warp tile 64x32.
// cp.async 3-stage ring buffer; padded smem stride 36 (conflict-free LDS:
// bank = 4*r0 + k mod 32, all 32 lanes distinct).
// NO in-loop cvt: A and W must already hold tf32-rounded fp32 values.
// ----------------------------------------------------------------------------
#define GBK 32
#define NSTAGE 3
#define SSTR 36
#define SBUF (128 * SSTR)
#define SMEM_BYTES (2 * NSTAGE * SBUF * 4)  // 110592 B

__global__ __launch_bounds__(256, 2) void gemm_tf32_kernel(
    const float* __restrict__ A, const float* __restrict__ W,
    const float* __restrict__ bias, float* __restrict__ C,
    int M, int N, int K)
{
    extern __shared__ float smem[];
    const uint32_t* As = (const uint32_t*)smem;
    const uint32_t* Bs = (const uint32_t*)(smem + NSTAGE * SBUF);
    const uint32_t smem_u32 = (uint32_t)__cvta_generic_to_shared(smem);

    const int tid   = threadIdx.x;
    const int lane  = tid & 31;
    const int warp  = tid >> 5;
    const int wm    = (warp >> 2) * 64;
    const int wn    = (warp & 3) * 32;
    const int bm    = blockIdx.y * 128;
    const int bn    = blockIdx.x * 128;

    const int lr  = tid >> 3;
    const int lk4 = (tid & 7) * 4;

    const float* Ap = A + (size_t)(bm + lr) * K + lk4;
    const float* Wp = W + (size_t)(bn + lr) * K + lk4;
    const uint32_t soA = smem_u32 + (uint32_t)((lr * SSTR + lk4) * 4);
    const uint32_t soB = soA + (uint32_t)(NSTAGE * SBUF * 4);

    float acc[4][4][4];
#pragma unroll
    for (int i = 0; i < 4; i++)
#pragma unroll
        for (int j = 0; j < 4; j++)
#pragma unroll
            for (int c = 0; c < 4; c++) acc[i][j][c] = 0.0f;

    const int T = K / GBK;

#define LOAD_TILE(t, buf)                                                      \
    do {                                                                       \
        const float* Apt = Ap + (size_t)(t) * GBK;                             \
        const float* Wpt = Wp + (size_t)(t) * GBK;                             \
        const uint32_t bo = (uint32_t)((buf) * SBUF * 4);                      \
        _Pragma("unroll")                                                      \
        for (int p = 0; p < 4; p++) {                                          \
            cp16(soA + bo + (uint32_t)(p * 32 * SSTR * 4),                     \
                 Apt + (size_t)(p * 32) * K);                                  \
            cp16(soB + bo + (uint32_t)(p * 32 * SSTR * 4),                     \
                 Wpt + (size_t)(p * 32) * K);                                  \
        }                                                                      \
        asm volatile("cp.async.commit_group;\n" ::: "memory");                 \
    } while (0)

    LOAD_TILE(0, 0);
    LOAD_TILE(1, 1);

    int buf = 0;
    for (int t = 0; t < T; t++) {
        if (t + 2 < T) {
            LOAD_TILE(t + 2, (buf + 2) % NSTAGE);
            asm volatile("cp.async.wait_group 2;\n" ::: "memory");
        } else if (t + 1 < T) {
            asm volatile("cp.async.wait_group 1;\n" ::: "memory");
        } else {
            asm volatile("cp.async.wait_group 0;\n" ::: "memory");
        }
        __syncthreads();

        const uint32_t* Asc = As + buf * SBUF;
        const uint32_t* Bsc = Bs + buf * SBUF;
#pragma unroll
        for (int ks = 0; ks < 4; ks++) {
            const int k0 = ks * 8;
            uint32_t af[4][4];
            uint32_t bf[4][2];
#pragma unroll
            for (int am = 0; am < 4; am++) {
                int r0 = wm + am * 16 + (lane >> 2);
                int c0 = k0 + (lane & 3);
                af[am][0] = Asc[r0 * SSTR + c0];
                af[am][1] = Asc[(r0 + 8) * SSTR + c0];
                af[am][2] = Asc[r0 * SSTR + c0 + 4];
                af[am][3] = Asc[(r0 + 8) * SSTR + c0 + 4];
            }
#pragma unroll
            for (int bnn = 0; bnn < 4; bnn++) {
                int col = wn + bnn * 8 + (lane >> 2);
                int kk  = k0 + (lane & 3);
                bf[bnn][0] = Bsc[col * SSTR + kk];
                bf[bnn][1] = Bsc[col * SSTR + kk + 4];
            }
#pragma unroll
            for (int am = 0; am < 4; am++)
#pragma unroll
                for (int bnn = 0; bnn < 4; bnn++)
                    mma_tf32(acc[am][bnn],
                             af[am][0], af[am][1], af[am][2], af[am][3],
                             bf[bnn][0], bf[bnn][1]);
        }
        __syncthreads();
        buf = (buf + 1) % NSTAGE;
    }

    float bv0[4], bv1[4];
#pragma unroll
    for (int bnn = 0; bnn < 4; bnn++) {
        int c0 = bn + wn + bnn * 8 + (lane & 3) * 2;
        bv0[bnn] = __ldg(&bias[c0]);
        bv1[bnn] = __ldg(&bias[c0 + 1]);
    }
#pragma unroll
    for (int am = 0; am < 4; am++) {
        int r0 = bm + wm + am * 16 + (lane >> 2);
#pragma unroll
        for (int bnn = 0; bnn < 4; bnn++) {
            int c0 = bn + wn + bnn * 8 + (lane & 3) * 2;
            float2 v01 = make_float2(acc[am][bnn][0] + bv0[bnn], acc[am][bnn][1] + bv1[bnn]);
            float2 v23 = make_float2(acc[am][bnn][2] + bv0[bnn], acc[am][bnn][3] + bv1[bnn]);
            *(float2*)&C[(size_t)r0 * N + c0]       = v01;
            *(float2*)&C[(size_t)(r0 + 8) * N + c0] = v23;
        }
    }
}

// ----------------------------------------------------------------------------
// zero g_kv (needed for atomic accumulation in split kv kernel)
// ----------------------------------------------------------------------------
__global__ void zero_kv_kernel()
{
    size_t i = (size_t)blockIdx.x * blockDim.x + threadIdx.x;
    if (i < (size_t)CB * CH * HD * HD) g_kv[i] = 0.0f;
}

// ----------------------------------------------------------------------------
// kv kernel: grid (B*H, KVSPLIT). Each block handles an S-chunk, computes a
// partial 64x64 kv and atomicAdds into g_kv. khat = k/||k|| per row.
// ----------------------------------------------------------------------------
#define KVSPLIT 8
#define KVCHUNK (CS / KVSPLIT)   // 512

__global__ __launch_bounds__(256) void kv_kernel()
{
    int bh = blockIdx.x;
    int b = bh / CH, h = bh % CH;
    int sbeg = blockIdx.y * KVCHUNK;
    const float* kbase = g_qkv + (size_t)b * CS * NQKV + CD     + h * HD;
    const float* vbase = g_qkv + (size_t)b * CS * NQKV + 2 * CD + h * HD;

    __shared__ float ks[32][HD];
    __shared__ float vs[32][HD];

    int tid  = threadIdx.x;
    int lane = tid & 31;
    int warp = tid >> 5;
    int ti = tid >> 4;   // 0..15
    int tj = tid & 15;   // 0..15

    float acc[4][4];
#pragma unroll
    for (int i = 0; i < 4; i++)
#pragma unroll
        for (int j = 0; j < 4; j++) acc[i][j] = 0.0f;

    for (int t0 = sbeg; t0 < sbeg + KVCHUNK; t0 += 32) {
        for (int i = tid; i < 32 * (HD / 4); i += 256) {
            int s  = i >> 4;
            int d4 = (i & 15) * 4;
            *(float4*)&ks[s][d4] = *(const float4*)&kbase[(size_t)(t0 + s) * NQKV + d4];
            *(float4*)&vs[s][d4] = *(const float4*)&vbase[(size_t)(t0 + s) * NQKV + d4];
        }
        __syncthreads();

#pragma unroll
        for (int rr = 0; rr < 4; rr++) {
            int r = warp * 4 + rr;
            float a = ks[r][lane], c = ks[r][lane + 32];
            float ns = a * a + c * c;
#pragma unroll
            for (int o = 16; o > 0; o >>= 1)
                ns += __shfl_xor_sync(0xffffffffu, ns, o);
            float inv = rsqrtf(ns);
            ks[r][lane] = a * inv;
            ks[r][lane + 32] = c * inv;
        }
        __syncthreads();

#pragma unroll 8
        for (int s = 0; s < 32; s++) {
            float4 ka = *(const float4*)&ks[s][ti * 4];
            float4 vb = *(const float4*)&vs[s][tj * 4];
            float kr[4] = {ka.x, ka.y, ka.z, ka.w};
            float vr[4] = {vb.x, vb.y, vb.z, vb.w};
#pragma unroll
            for (int i = 0; i < 4; i++)
#pragma unroll
                for (int j = 0; j < 4; j++)
                    acc[i][j] += kr[i] * vr[j];
        }
        __syncthreads();
    }

    float* kvout = g_kv + (size_t)bh * HD * HD;
#pragma unroll
    for (int i = 0; i < 4; i++)
#pragma unroll
        for (int j = 0; j < 4; j++)
            atomicAdd(&kvout[(ti * 4 + i) * HD + tj * 4 + j], acc[i][j]);
}

// ----------------------------------------------------------------------------
// out kernel: v tile (128+8 rows, zero-padded halo) staged in smem; conv and
// 0.5v term served from smem. Writes tf32-ROUNDED att (feeds GEMM2 A).
// ----------------------------------------------------------------------------
#define VROWS (128 + CKS - 1)   // 136
#define OUT_SMEM_FLOATS (HD * HD + VROWS * HD + 16)
#define OUT_SMEM_BYTES  (OUT_SMEM_FLOATS * 4)   // 51264 B

__global__ __launch_bounds__(256) void out_kernel(const float* __restrict__ wdconv)
{
    extern __shared__ float osm[];
    float* kvs   = osm;                 // [64*64]
    float* vsm   = osm + HD * HD;       // [136][64]
    float* wconv = vsm + VROWS * HD;    // [9]

    int bh = blockIdx.x;
    int b = bh / CH, h = bh % CH;
    int s0 = blockIdx.y * 128;

    int tid = threadIdx.x;
    int lane = tid & 31;
    int warp = tid >> 5;

    const float* qbase = g_qkv + (size_t)b * CS * NQKV + h * HD;
    const float* vbase = g_qkv + (size_t)b * CS * NQKV + 2 * CD + h * HD;

    for (int i = tid; i < HD * HD; i += 256)
        kvs[i] = g_kv[(size_t)bh * HD * HD + i];
    if (tid < CKS) wconv[tid] = wdconv[h * CKS + tid];

    for (int i = tid; i < VROWS * (HD / 4); i += 256) {
        int r  = i >> 4;
        int d4 = (i & 15) * 4;
        int s  = s0 + r - CPAD;
        float4 val = make_float4(0.f, 0.f, 0.f, 0.f);
        if (s >= 0 && s < CS)
            val = *(const float4*)&vbase[(size_t)s * NQKV + d4];
        *(float4*)&vsm[r * HD + d4] = val;
    }
    __syncthreads();

    const float invpi = 0.31830988618379067f;

    for (int r = warp; r < 128; r += 8) {
        int s = s0 + r;
        const float* qrow = qbase + (size_t)s * NQKV;

        float q0 = qrow[lane], q1 = qrow[lane + 32];
        float nq = q0 * q0 + q1 * q1;
#pragma unroll
        for (int o = 16; o > 0; o >>= 1)
            nq += __shfl_xor_sync(0xffffffffu, nq, o);
        float inq = rsqrtf(nq);
        q0 *= inq; q1 *= inq;

        float a0 = 0.0f, a1 = 0.0f;
#pragma unroll
        for (int dd = 0; dd < 32; dd++) {
            float qv = __shfl_sync(0xffffffffu, q0, dd);
            a0 += qv * kvs[dd * HD + lane];
            a1 += qv * kvs[dd * HD + lane + 32];
        }
#pragma unroll
        for (int dd = 0; dd < 32; dd++) {
            float qv = __shfl_sync(0xffffffffu, q1, dd);
            a0 += qv * kvs[(dd + 32) * HD + lane];
            a1 += qv * kvs[(dd + 32) * HD + lane + 32];
        }

        float v0 = vsm[(r + CPAD) * HD + lane];
        float v1 = vsm[(r + CPAD) * HD + lane + 32];
        float o0 = 0.5f * v0 + invpi * a0;
        float o1 = 0.5f * v1 + invpi * a1;
        float no = o0 * o0 + o1 * o1;
#pragma unroll
        for (int o = 16; o > 0; o >>= 1)
            no += __shfl_xor_sync(0xffffffffu, no, o);
        float ino = rsqrtf(no);
        o0 *= ino; o1 *= ino;

        float c0 = 0.0f, c1 = 0.0f;
#pragma unroll
        for (int t = 0; t < CKS; t++) {
            float w = wconv[t];
            c0 += w * vsm[(r + t) * HD + lane];
            c1 += w * vsm[(r + t) * HD + lane + 32];
        }
        o0 += c0; o1 += c1;

        // write tf32-rounded (GEMM2 would round these anyway; saves in-GEMM cvt)
        float* orow = g_att + (size_t)(b * CS + s) * CD + h * HD;
        orow[lane]      = __uint_as_float(f2tf32(o0));
        orow[lane + 32] = __uint_as_float(f2tf32(o1));
    }
}

// ----------------------------------------------------------------------------
// Launch
// ----------------------------------------------------------------------------
extern "C" void kernel_launch(void* const* d_in, const int* in_sizes, int n_in,
                              void* d_out, int out_size)
{
    (void)in_sizes; (void)n_in; (void)out_size;
    const float* x      = (const float*)d_in[0];
    const float* w_qkv  = (const float*)d_in[1];
    const float* b_qkv  = (const float*)d_in[2];
    const float* w_proj = (const float*)d_in[3];
    const float* b_proj = (const float*)d_in[4];
    const float* wdconv = (const float*)d_in[5];
    float* out = (float*)d_out;

    float *qkv_ptr = nullptr, *att_ptr = nullptr, *xt_ptr = nullptr;
    float *wq_ptr = nullptr, *wp_ptr = nullptr;
    cudaGetSymbolAddress((void**)&qkv_ptr, g_qkv);
    cudaGetSymbolAddress((void**)&att_ptr, g_att);
    cudaGetSymbolAddress((void**)&xt_ptr,  g_xt);
    cudaGetSymbolAddress((void**)&wq_ptr,  g_wq);
    cudaGetSymbolAddress((void**)&wp_ptr,  g_wp);

    // Unconditional (no static guards allowed). Host-side, capture-safe.
    cudaFuncSetAttribute(gemm_tf32_kernel,
                         cudaFuncAttributeMaxDynamicSharedMemorySize, SMEM_BYTES);
    cudaFuncSetAttribute(out_kernel,
                         cudaFuncAttributeMaxDynamicSharedMemorySize, OUT_SMEM_BYTES);

    dim3 blk(256);

    // 0) pre-round operands to tf32
    {
        size_t n4x = (size_t)MTOT * CD / 4;
        cvt_tf32_kernel<<<(unsigned)((n4x + 255) / 256), blk>>>(x, xt_ptr, n4x);
        size_t n4q = (size_t)NQKV * CD / 4;
        cvt_tf32_kernel<<<(unsigned)((n4q + 255) / 256), blk>>>(w_qkv, wq_ptr, n4q);
        size_t n4p = (size_t)CD * CD / 4;
        cvt_tf32_kernel<<<(unsigned)((n4p + 255) / 256), blk>>>(w_proj, wp_ptr, n4p);
    }

    // 1) QKV projection: [65536,2304] = xt @ wq^T + b
    dim3 g1(NQKV / 128, MTOT / 128);
    gemm_tf32_kernel<<<g1, blk, SMEM_BYTES>>>(xt_ptr, wq_ptr, b_qkv, qkv_ptr, MTOT, NQKV, CD);

    // 2) kv = khat^T v per (b,h), split over S with atomic merge
    zero_kv_kernel<<<(CB * CH * HD * HD + 1023) / 1024, 1024>>>();
    dim3 g2(CB * CH, KVSPLIT);
    kv_kernel<<<g2, blk>>>();

    // 3) attention epilogue + conv + transpose (smem-staged v, tf32-rounded out)
    dim3 g3(CB * CH, CS / 128);
    out_kernel<<<g3, blk, OUT_SMEM_BYTES>>>(wdconv);

    // 4) output projection: [65536,768] = att @ wp^T + b
    dim3 g4(CD / 128, MTOT / 128);
    gemm_tf32_kernel<<<g4, blk, SMEM_BYTES>>>(att_ptr, wp_ptr, b_proj, out, MTOT, CD, CD);
}